// round 2
// baseline (speedup 1.0000x reference)
#include <cuda_runtime.h>

// Problem constants (match reference)
#define FB 2
#define FC 256
#define FH 96
#define FW 96
#define FHW (FH * FW)
#define PO 7
#define NBIN 49           // 7*7
#define NROIS 512
#define CG 64             // channel groups of float4 (256/4)
#define OUT_PER_ROI (FC * NBIN) // 12544 floats
#define NB0 25            // bins in pass 0
#define NB1 24            // bins in pass 1
#define SLAB (NB0 * FC)   // 6400 floats = 25.6KB staging slab

#define SPATIAL_SCALE 0.0625f
#define TRANS_STD 0.1f

// NHWC scratch: [B][H][W][C] floats = 2*96*96*256*4B ~= 18.9 MB (L2-resident)
__device__ float g_nhwc[FB * FHW * FC];

// ---------------------------------------------------------------------------
// Kernel 1: tiled NCHW -> NHWC transpose (coalesced both sides)
// ---------------------------------------------------------------------------
__global__ __launch_bounds__(256) void nchw_to_nhwc_kernel(const float* __restrict__ in) {
    __shared__ float tile[32][33];
    const int b   = blockIdx.z;
    const int hw0 = blockIdx.x * 32;
    const int c0  = blockIdx.y * 32;
    const int tx  = threadIdx.x;
    const int ty  = threadIdx.y;

    const float* src = in + (size_t)b * FC * FHW;
    float* dst = g_nhwc + (size_t)b * FHW * FC;

#pragma unroll
    for (int i = 0; i < 4; i++) {
        int c = c0 + ty + i * 8;
        tile[ty + i * 8][tx] = src[(size_t)c * FHW + hw0 + tx];
    }
    __syncthreads();
#pragma unroll
    for (int i = 0; i < 4; i++) {
        int hw = hw0 + ty + i * 8;
        dst[(size_t)hw * FC + c0 + tx] = tile[tx][ty + i * 8];
    }
}

// ---------------------------------------------------------------------------
// Kernel 2: one CTA per ROI, two bin-passes to halve smem (occupancy 6-7 CTA/SM)
// Branch-free gathers: all 16 float4 loads per item issued unconditionally so
// ptxas can batch them (weights are zero for invalid samples; coords clamped).
// ---------------------------------------------------------------------------
__global__ __launch_bounds__(256, 6) void deform_psroi_kernel(
    const float* __restrict__ rois,
    const float* __restrict__ trans,
    float* __restrict__ out)
{
    __shared__ float4 wgt[4 * NBIN];
    __shared__ int4   offs[4 * NBIN];
    __shared__ float  invc[NBIN];
    __shared__ int    sBase;
    extern __shared__ float outbuf[];   // SLAB floats (25.6KB)

    const int n   = blockIdx.x;
    const int tid = threadIdx.x;

    // ---- Phase 1: geometry (49 threads) ----
    if (tid < NBIN) {
        const float* r = rois + n * 5;
        float x1 = rintf(r[1]) * SPATIAL_SCALE - 0.5f;
        float y1 = rintf(r[2]) * SPATIAL_SCALE - 0.5f;
        float x2 = (rintf(r[3]) + 1.0f) * SPATIAL_SCALE - 0.5f;
        float y2 = (rintf(r[4]) + 1.0f) * SPATIAL_SCALE - 0.5f;
        float rw = fmaxf(x2 - x1, 0.1f);
        float rh = fmaxf(y2 - y1, 0.1f);
        float bw = rw * (1.0f / PO), bh = rh * (1.0f / PO);
        float sw = bw * 0.5f,        sh = bh * 0.5f;

        int ph = tid / PO;
        int pw = tid - ph * PO;
        float tx = trans[((n * 2 + 0) * PO + ph) * PO + pw] * TRANS_STD;
        float ty = trans[((n * 2 + 1) * PO + ph) * PO + pw] * TRANS_STD;
        float wst = pw * bw + x1 + tx * rw;
        float hst = ph * bh + y1 + ty * rh;

        int cnt = 0;
#pragma unroll
        for (int s = 0; s < 4; s++) {
            float w = wst + (float)(s & 1) * sw;
            float h = hst + (float)(s >> 1) * sh;
            bool valid = (w >= -0.5f) && (w <= (float)FW - 0.5f) &&
                         (h >= -0.5f) && (h <= (float)FH - 0.5f);
            float wc = fminf(fmaxf(w, 0.0f), (float)FW - 1.0f);
            float hc = fminf(fmaxf(h, 0.0f), (float)FH - 1.0f);
            float x0f = floorf(wc), y0f = floorf(hc);
            float dx = wc - x0f,    dy = hc - y0f;
            int x0 = (int)x0f,      y0 = (int)y0f;
            int xI = (int)ceilf(wc), yI = (int)ceilf(hc);
            float w00 = (1.0f - dx) * (1.0f - dy);
            float w01 = dx * (1.0f - dy);
            float w10 = (1.0f - dx) * dy;
            float w11 = dx * dy;
            if (!valid) { w00 = w01 = w10 = w11 = 0.0f; } else { cnt++; }
            wgt[tid * 4 + s]  = make_float4(w00, w01, w10, w11);
            offs[tid * 4 + s] = make_int4((y0 * FW + x0) * CG,
                                          (y0 * FW + xI) * CG,
                                          (yI * FW + x0) * CG,
                                          (yI * FW + xI) * CG);
        }
        invc[tid] = cnt ? 1.0f / (float)cnt : 0.0f;
        if (tid == 0) sBase = ((int)r[0]) * (FHW * CG);
    }
    __syncthreads();

    const float4* src = (const float4*)g_nhwc;
    const int base = sBase;

#pragma unroll
    for (int pass = 0; pass < 2; pass++) {
        const int binBase = pass ? NB0 : 0;
        const int nb      = pass ? NB1 : NB0;
        const int items   = nb * CG;

        // ---- Phase 2: branch-free gather + blend ----
        for (int it = tid; it < items; it += 256) {
            int bl  = it >> 6;       // local bin (warp-uniform)
            int cg  = it & 63;
            int bin = binBase + bl;

            float ax = 0.f, ay = 0.f, az = 0.f, aw = 0.f;
#pragma unroll
            for (int s = 0; s < 4; s++) {
                float4 wv = wgt[bin * 4 + s];
                int4   o  = offs[bin * 4 + s];
                float4 v00 = src[base + o.x + cg];
                float4 v01 = src[base + o.y + cg];
                float4 v10 = src[base + o.z + cg];
                float4 v11 = src[base + o.w + cg];
                ax += wv.x * v00.x + wv.y * v01.x + wv.z * v10.x + wv.w * v11.x;
                ay += wv.x * v00.y + wv.y * v01.y + wv.z * v10.y + wv.w * v11.y;
                az += wv.x * v00.z + wv.y * v01.z + wv.z * v10.z + wv.w * v11.z;
                aw += wv.x * v00.w + wv.y * v01.w + wv.z * v10.w + wv.w * v11.w;
            }
            float ic = invc[bin];
            int c = cg * 4;
            outbuf[(c + 0) * nb + bl] = ax * ic;
            outbuf[(c + 1) * nb + bl] = ay * ic;
            outbuf[(c + 2) * nb + bl] = az * ic;
            outbuf[(c + 3) * nb + bl] = aw * ic;
        }
        __syncthreads();

        // ---- Phase 3: coalesced writeback of the half-slab ----
        {
            const int total = FC * nb;
            float* dst = out + (size_t)n * OUT_PER_ROI + binBase;
            for (int i = tid; i < total; i += 256) {
                int c  = i / nb;
                int bl = i - c * nb;
                dst[c * NBIN + bl] = outbuf[i];
            }
        }
        __syncthreads();
    }
}

// ---------------------------------------------------------------------------
// Launch
// ---------------------------------------------------------------------------
extern "C" void kernel_launch(void* const* d_in, const int* in_sizes, int n_in,
                              void* d_out, int out_size) {
    const float* bottom_data  = (const float*)d_in[0];
    const float* bottom_rois  = (const float*)d_in[1];
    const float* bottom_trans = (const float*)d_in[2];
    float* out = (float*)d_out;

    nchw_to_nhwc_kernel<<<dim3(FHW / 32, FC / 32, FB), dim3(32, 8)>>>(bottom_data);
    deform_psroi_kernel<<<NROIS, 256, SLAB * sizeof(float)>>>(bottom_rois, bottom_trans, out);
}

// round 3
// speedup vs baseline: 1.3710x; 1.3710x over previous
#include <cuda_runtime.h>

// Problem constants (match reference)
#define FB 2
#define FC 256
#define FH 96
#define FW 96
#define FHW (FH * FW)
#define PO 7
#define NBIN 49
#define NROIS 512
#define CG 64                    // channel groups of float4 (256/4)
#define OUT_PER_ROI (FC * NBIN)  // 12544 floats
#define NBMAX 25                 // max bins per half-CTA
#define ROWSTRIDE 260            // slab row stride in floats (16B aligned, %32==4)
#define SLAB_BYTES (NBMAX * ROWSTRIDE * 4)  // 26000 B

#define SPATIAL_SCALE 0.0625f
#define TRANS_STD 0.1f

// NHWC scratch: [B][H][W][C] floats ~= 18.9 MB (L2-resident)
__device__ float g_nhwc[FB * FHW * FC];

// ---------------------------------------------------------------------------
// Kernel 1: tiled NCHW -> NHWC transpose (coalesced both sides)
// ---------------------------------------------------------------------------
__global__ __launch_bounds__(256) void nchw_to_nhwc_kernel(const float* __restrict__ in) {
    __shared__ float tile[32][33];
    const int b   = blockIdx.z;
    const int hw0 = blockIdx.x * 32;
    const int c0  = blockIdx.y * 32;
    const int tx  = threadIdx.x;
    const int ty  = threadIdx.y;

    const float* src = in + (size_t)b * FC * FHW;
    float* dst = g_nhwc + (size_t)b * FHW * FC;

#pragma unroll
    for (int i = 0; i < 4; i++) {
        int c = c0 + ty + i * 8;
        tile[ty + i * 8][tx] = src[(size_t)c * FHW + hw0 + tx];
    }
    __syncthreads();
#pragma unroll
    for (int i = 0; i < 4; i++) {
        int hw = hw0 + ty + i * 8;
        dst[(size_t)hw * FC + c0 + tx] = tile[tx][ty + i * 8];
    }
}

// ---------------------------------------------------------------------------
// Kernel 2: TWO CTAs per ROI (half the bins each) -> grid 1024, ~7 CTAs/SM.
//   Phase 1: <=25 threads compute this half's bin geometry into smem.
//   Phase 2: items = nb*64 (bin, float4-channel-group); 16 unconditional
//            coalesced float4 gathers; ONE conflict-free STS.128 per item.
//   Phase 3: division-free warp-per-channel writeback, contiguous STG.
// ---------------------------------------------------------------------------
__global__ __launch_bounds__(256, 5) void deform_psroi_kernel(
    const float* __restrict__ rois,
    const float* __restrict__ trans,
    float* __restrict__ out)
{
    __shared__ float4 wgt[4 * NBMAX];
    __shared__ int4   offs[4 * NBMAX];
    __shared__ float  invc[NBMAX];
    __shared__ int    sBase;
    extern __shared__ float outbuf[];   // [NBMAX][ROWSTRIDE]

    const int cta  = blockIdx.x;
    const int n    = cta >> 1;          // roi
    const int half = cta & 1;
    const int binBase = half ? NBMAX : 0;
    const int nb      = half ? (NBIN - NBMAX) : NBMAX;   // 24 or 25
    const int tid  = threadIdx.x;

    // ---- Phase 1: geometry for this half's bins ----
    if (tid < nb) {
        const float* r = rois + n * 5;
        float x1 = rintf(r[1]) * SPATIAL_SCALE - 0.5f;
        float y1 = rintf(r[2]) * SPATIAL_SCALE - 0.5f;
        float x2 = (rintf(r[3]) + 1.0f) * SPATIAL_SCALE - 0.5f;
        float y2 = (rintf(r[4]) + 1.0f) * SPATIAL_SCALE - 0.5f;
        float rw = fmaxf(x2 - x1, 0.1f);
        float rh = fmaxf(y2 - y1, 0.1f);
        float bw = rw * (1.0f / PO), bh = rh * (1.0f / PO);
        float sw = bw * 0.5f,        sh = bh * 0.5f;

        int bin = binBase + tid;
        int ph = bin / PO;               // div by constant 7 -> mul
        int pw = bin - ph * PO;
        float tx = trans[((n * 2 + 0) * PO + ph) * PO + pw] * TRANS_STD;
        float ty = trans[((n * 2 + 1) * PO + ph) * PO + pw] * TRANS_STD;
        float wst = pw * bw + x1 + tx * rw;
        float hst = ph * bh + y1 + ty * rh;

        int cnt = 0;
#pragma unroll
        for (int s = 0; s < 4; s++) {
            float w = wst + (float)(s & 1) * sw;
            float h = hst + (float)(s >> 1) * sh;
            bool valid = (w >= -0.5f) && (w <= (float)FW - 0.5f) &&
                         (h >= -0.5f) && (h <= (float)FH - 0.5f);
            float wc = fminf(fmaxf(w, 0.0f), (float)FW - 1.0f);
            float hc = fminf(fmaxf(h, 0.0f), (float)FH - 1.0f);
            float x0f = floorf(wc), y0f = floorf(hc);
            float dx = wc - x0f,    dy = hc - y0f;
            int x0 = (int)x0f,      y0 = (int)y0f;
            int xI = (int)ceilf(wc), yI = (int)ceilf(hc);
            float w00 = (1.0f - dx) * (1.0f - dy);
            float w01 = dx * (1.0f - dy);
            float w10 = (1.0f - dx) * dy;
            float w11 = dx * dy;
            if (!valid) { w00 = w01 = w10 = w11 = 0.0f; } else { cnt++; }
            wgt[tid * 4 + s]  = make_float4(w00, w01, w10, w11);
            offs[tid * 4 + s] = make_int4((y0 * FW + x0) * CG,
                                          (y0 * FW + xI) * CG,
                                          (yI * FW + x0) * CG,
                                          (yI * FW + xI) * CG);
        }
        invc[tid] = cnt ? 1.0f / (float)cnt : 0.0f;
        if (tid == 0) sBase = ((int)r[0]) * (FHW * CG);
    }
    __syncthreads();

    const float4* src = (const float4*)g_nhwc;
    const int base = sBase;
    const int items = nb * CG;          // 1600 or 1536

    // ---- Phase 2: branch-free gather + blend, one STS.128 per item ----
    for (int it = tid; it < items; it += 256) {
        int bl = it >> 6;               // local bin (warp-uniform)
        int cg = it & 63;

        float ax = 0.f, ay = 0.f, az = 0.f, aw = 0.f;
#pragma unroll
        for (int s = 0; s < 4; s++) {
            float4 wv = wgt[bl * 4 + s];
            int4   o  = offs[bl * 4 + s];
            float4 v00 = src[base + o.x + cg];
            float4 v01 = src[base + o.y + cg];
            float4 v10 = src[base + o.z + cg];
            float4 v11 = src[base + o.w + cg];
            ax += wv.x * v00.x + wv.y * v01.x + wv.z * v10.x + wv.w * v11.x;
            ay += wv.x * v00.y + wv.y * v01.y + wv.z * v10.y + wv.w * v11.y;
            az += wv.x * v00.z + wv.y * v01.z + wv.z * v10.z + wv.w * v11.z;
            aw += wv.x * v00.w + wv.y * v01.w + wv.z * v10.w + wv.w * v11.w;
        }
        float ic = invc[bl];
        // conflict-free STS.128: lanes share bl, consecutive cg
        *(float4*)&outbuf[bl * ROWSTRIDE + cg * 4] =
            make_float4(ax * ic, ay * ic, az * ic, aw * ic);
    }
    __syncthreads();

    // ---- Phase 3: division-free writeback. Warp w -> channels w*32..w*32+31;
    //      lane = local bin -> contiguous global store per channel. ----
    {
        const int warp = tid >> 5;
        const int lane = tid & 31;
        float* dst = out + (size_t)n * OUT_PER_ROI + binBase;
        if (lane < nb) {
#pragma unroll 4
            for (int i = 0; i < 32; i++) {
                int c = warp * 32 + i;
                dst[c * NBIN + lane] = outbuf[lane * ROWSTRIDE + c];
            }
        }
    }
}

// ---------------------------------------------------------------------------
// Launch
// ---------------------------------------------------------------------------
extern "C" void kernel_launch(void* const* d_in, const int* in_sizes, int n_in,
                              void* d_out, int out_size) {
    const float* bottom_data  = (const float*)d_in[0];
    const float* bottom_rois  = (const float*)d_in[1];
    const float* bottom_trans = (const float*)d_in[2];
    float* out = (float*)d_out;

    nchw_to_nhwc_kernel<<<dim3(FHW / 32, FC / 32, FB), dim3(32, 8)>>>(bottom_data);
    deform_psroi_kernel<<<NROIS * 2, 256, SLAB_BYTES>>>(bottom_rois, bottom_trans, out);
}

// round 6
// speedup vs baseline: 1.4519x; 1.0590x over previous
#include <cuda_runtime.h>

// Problem constants (match reference)
#define FB 2
#define FC 256
#define FH 96
#define FW 96
#define FHW (FH * FW)
#define PO 7
#define NBIN 49
#define NROIS 512
#define CG 64                    // channel groups of float4 (256/4)
#define OUT_PER_ROI (FC * NBIN)  // 12544 floats
#define NB 7                     // bins per CTA (one pooled row)
#define ROWSTRIDE 260            // slab row stride in floats (16B-multiple, %32==4)
#define SLAB_FLOATS (NB * ROWSTRIDE)

#define SPATIAL_SCALE 0.0625f
#define TRANS_STD 0.1f

// NHWC scratch: [B][H][W][C] floats ~= 18.9 MB (L2-resident)
__device__ float g_nhwc[FB * FHW * FC];

// ---------------------------------------------------------------------------
// Kernel 1: tiled NCHW -> NHWC transpose (coalesced both sides)
// ---------------------------------------------------------------------------
__global__ __launch_bounds__(256) void nchw_to_nhwc_kernel(const float* __restrict__ in) {
    __shared__ float tile[32][33];
    const int b   = blockIdx.z;
    const int hw0 = blockIdx.x * 32;
    const int c0  = blockIdx.y * 32;
    const int tx  = threadIdx.x;
    const int ty  = threadIdx.y;

    const float* src = in + (size_t)b * FC * FHW;
    float* dst = g_nhwc + (size_t)b * FHW * FC;

#pragma unroll
    for (int i = 0; i < 4; i++) {
        int c = c0 + ty + i * 8;
        tile[ty + i * 8][tx] = src[(size_t)c * FHW + hw0 + tx];
    }
    __syncthreads();
#pragma unroll
    for (int i = 0; i < 4; i++) {
        int hw = hw0 + ty + i * 8;
        dst[(size_t)hw * FC + c0 + tx] = tile[tx][ty + i * 8];
    }
}

// ---------------------------------------------------------------------------
// Kernel 2: SEVEN CTAs per ROI (one pooled row = 7 bins each) -> grid 3584.
//   Phase 1: 7 threads compute this row's bin geometry; batch base folded
//            into the precomputed offsets.
//   Phase 2: 448 items = (bin, float4-channel-group); 16 unconditional
//            coalesced float4 gathers; one conflict-free STS.128 per item.
//   Phase 3: const-7 division writeback, lanes on consecutive i.
// ---------------------------------------------------------------------------
__global__ __launch_bounds__(256, 6) void deform_psroi_kernel(
    const float* __restrict__ rois,
    const float* __restrict__ trans,
    float* __restrict__ out)
{
    __shared__ float4 wgt[4 * NB];
    __shared__ int4   offs[4 * NB];
    __shared__ float  invc[NB];
    __shared__ __align__(16) float outbuf[SLAB_FLOATS];   // [NB][ROWSTRIDE], 16B base

    const int cta  = blockIdx.x;
    const int n    = cta / PO;       // roi (const div)
    const int part = cta - n * PO;   // pooled row ph
    const int tid  = threadIdx.x;

    // ---- Phase 1: geometry for 7 bins of row `part` (ph=part, pw=tid) ----
    if (tid < NB) {
        const float* r = rois + n * 5;
        const int base = ((int)r[0]) * (FHW * CG);   // batch offset, float4 units
        float x1 = rintf(r[1]) * SPATIAL_SCALE - 0.5f;
        float y1 = rintf(r[2]) * SPATIAL_SCALE - 0.5f;
        float x2 = (rintf(r[3]) + 1.0f) * SPATIAL_SCALE - 0.5f;
        float y2 = (rintf(r[4]) + 1.0f) * SPATIAL_SCALE - 0.5f;
        float rw = fmaxf(x2 - x1, 0.1f);
        float rh = fmaxf(y2 - y1, 0.1f);
        float bw = rw * (1.0f / PO), bh = rh * (1.0f / PO);
        float sw = bw * 0.5f,        sh = bh * 0.5f;

        const int ph = part, pw = tid;
        float tx = trans[((n * 2 + 0) * PO + ph) * PO + pw] * TRANS_STD;
        float ty = trans[((n * 2 + 1) * PO + ph) * PO + pw] * TRANS_STD;
        float wst = pw * bw + x1 + tx * rw;
        float hst = ph * bh + y1 + ty * rh;

        int cnt = 0;
#pragma unroll
        for (int s = 0; s < 4; s++) {
            float w = wst + (float)(s & 1) * sw;
            float h = hst + (float)(s >> 1) * sh;
            bool valid = (w >= -0.5f) && (w <= (float)FW - 0.5f) &&
                         (h >= -0.5f) && (h <= (float)FH - 0.5f);
            float wc = fminf(fmaxf(w, 0.0f), (float)FW - 1.0f);
            float hc = fminf(fmaxf(h, 0.0f), (float)FH - 1.0f);
            float x0f = floorf(wc), y0f = floorf(hc);
            float dx = wc - x0f,    dy = hc - y0f;
            int x0 = (int)x0f,      y0 = (int)y0f;
            int xI = (int)ceilf(wc), yI = (int)ceilf(hc);
            float w00 = (1.0f - dx) * (1.0f - dy);
            float w01 = dx * (1.0f - dy);
            float w10 = (1.0f - dx) * dy;
            float w11 = dx * dy;
            if (!valid) { w00 = w01 = w10 = w11 = 0.0f; } else { cnt++; }
            wgt[tid * 4 + s]  = make_float4(w00, w01, w10, w11);
            offs[tid * 4 + s] = make_int4(base + (y0 * FW + x0) * CG,
                                          base + (y0 * FW + xI) * CG,
                                          base + (yI * FW + x0) * CG,
                                          base + (yI * FW + xI) * CG);
        }
        invc[tid] = cnt ? 1.0f / (float)cnt : 0.0f;
    }
    __syncthreads();

    const float4* __restrict__ src = (const float4*)g_nhwc;

    // ---- Phase 2: branch-free gather + blend (448 items, <=2 per thread) ----
    for (int it = tid; it < NB * CG; it += 256) {
        int bl = it >> 6;               // local bin (warp-uniform)
        int cg = it & 63;

        float ax = 0.f, ay = 0.f, az = 0.f, aw = 0.f;
#pragma unroll
        for (int s = 0; s < 4; s++) {
            float4 wv = wgt[bl * 4 + s];
            int4   o  = offs[bl * 4 + s];
            float4 v00 = src[o.x + cg];
            float4 v01 = src[o.y + cg];
            float4 v10 = src[o.z + cg];
            float4 v11 = src[o.w + cg];
            ax += wv.x * v00.x + wv.y * v01.x + wv.z * v10.x + wv.w * v11.x;
            ay += wv.x * v00.y + wv.y * v01.y + wv.z * v10.y + wv.w * v11.y;
            az += wv.x * v00.z + wv.y * v01.z + wv.z * v10.z + wv.w * v11.z;
            aw += wv.x * v00.w + wv.y * v01.w + wv.z * v10.w + wv.w * v11.w;
        }
        float ic = invc[bl];
        *(float4*)&outbuf[bl * ROWSTRIDE + cg * 4] =
            make_float4(ax * ic, ay * ic, az * ic, aw * ic);
    }
    __syncthreads();

    // ---- Phase 3: writeback 1792 floats; i consecutive across lanes,
    //      c=i/7 and bl=i%7 are const-divisions (IMAD). ----
    {
        float* dst = out + (size_t)n * OUT_PER_ROI + part * NB;
#pragma unroll
        for (int k = 0; k < 7; k++) {
            int i  = tid + k * 256;
            int c  = i / NB;
            int bl = i - c * NB;
            dst[c * NBIN + bl] = outbuf[bl * ROWSTRIDE + c];
        }
    }
}

// ---------------------------------------------------------------------------
// Launch
// ---------------------------------------------------------------------------
extern "C" void kernel_launch(void* const* d_in, const int* in_sizes, int n_in,
                              void* d_out, int out_size) {
    const float* bottom_data  = (const float*)d_in[0];
    const float* bottom_rois  = (const float*)d_in[1];
    const float* bottom_trans = (const float*)d_in[2];
    float* out = (float*)d_out;

    nchw_to_nhwc_kernel<<<dim3(FHW / 32, FC / 32, FB), dim3(32, 8)>>>(bottom_data);
    deform_psroi_kernel<<<NROIS * PO, 256>>>(bottom_rois, bottom_trans, out);
}